// round 4
// baseline (speedup 1.0000x reference)
#include <cuda_runtime.h>
#include <cuda_bf16.h>
#include <cstdint>
#include <cstddef>

// ---------------------------------------------------------------------------
// KSSM layer: B=4, S=4096, D=1024
// GEMMs: bf16x3 (hi/lo split) on mma.sync HMMA, 3-stage cp.async pipeline.
// Scan: chunked complex scan (64 chunks x 64 steps).
// ---------------------------------------------------------------------------

#define BDIM 4
#define SDIM 4096
#define DDIM 1024
#define MDIM (BDIM * SDIM)        // 16384
#define PRE_LD 5120               // [alpha | omega | Bx(interleaved) | dt]
#define NCH 64
#define LCH 64

// GEMM tiling
#define BM 128
#define BN 128
#define BK 64
#define NSTAGE 3
#define STAGE_BYTES 65536         // 4 operand tiles x 16KB
#define SM_TOTAL (NSTAGE * STAGE_BYTES)

typedef unsigned short u16;

// scratch (static device memory)
__device__ __align__(256) float g_pre[(size_t)MDIM * PRE_LD];
__device__ __align__(256) float g_P[(size_t)BDIM * NCH * 2 * DDIM];
__device__ __align__(256) float g_Q[(size_t)BDIM * NCH * 2 * DDIM];
__device__ __align__(256) float g_h0[(size_t)BDIM * NCH * 2 * DDIM];
__device__ __align__(256) u16 g_xh[(size_t)MDIM * DDIM];
__device__ __align__(256) u16 g_xl[(size_t)MDIM * DDIM];
__device__ __align__(256) u16 g_sth[(size_t)MDIM * 2 * DDIM];
__device__ __align__(256) u16 g_stl[(size_t)MDIM * 2 * DDIM];
__device__ __align__(256) u16 g_Wt_hi[(size_t)PRE_LD * DDIM];    // [n][k]
__device__ __align__(256) u16 g_Wt_lo[(size_t)PRE_LD * DDIM];
__device__ __align__(256) u16 g_WCt_hi[(size_t)DDIM * 2 * DDIM]; // [n][k=2048]
__device__ __align__(256) u16 g_WCt_lo[(size_t)DDIM * 2 * DDIM];
__device__ __align__(256) float g_bias_cat[PRE_LD];

// ---------------------------------------------------------------------------
// helpers
// ---------------------------------------------------------------------------
__device__ __forceinline__ uint32_t smem_u32(const void* p) {
    uint32_t a;
    asm("{ .reg .u64 t; cvta.to.shared.u64 t, %1; cvt.u32.u64 %0, t; }" : "=r"(a) : "l"(p));
    return a;
}

__device__ __forceinline__ uint32_t swz(uint32_t o) { return o ^ ((o >> 3) & 0x70); }

#define CPASYNC16(dst, src) \
    asm volatile("cp.async.cg.shared.global [%0], [%1], 16;" :: "r"(dst), "l"(src))
#define CPASYNC_COMMIT() asm volatile("cp.async.commit_group;" ::: "memory")
#define CPASYNC_WAIT1()  asm volatile("cp.async.wait_group 1;" ::: "memory")
#define CPASYNC_WAIT0()  asm volatile("cp.async.wait_group 0;" ::: "memory")

__device__ __forceinline__ void ldsm_x4(uint32_t* r, uint32_t addr) {
    asm volatile("ldmatrix.sync.aligned.m8n8.x4.shared.b16 {%0,%1,%2,%3}, [%4];"
                 : "=r"(r[0]), "=r"(r[1]), "=r"(r[2]), "=r"(r[3]) : "r"(addr));
}

__device__ __forceinline__ void mma_bf16(float* c, const uint32_t* a, const uint32_t* b) {
    asm volatile(
        "mma.sync.aligned.m16n8k16.row.col.f32.bf16.bf16.f32 "
        "{%0,%1,%2,%3}, {%4,%5,%6,%7}, {%8,%9}, {%0,%1,%2,%3};"
        : "+f"(c[0]), "+f"(c[1]), "+f"(c[2]), "+f"(c[3])
        : "r"(a[0]), "r"(a[1]), "r"(a[2]), "r"(a[3]), "r"(b[0]), "r"(b[1]));
}

// ---------------------------------------------------------------------------
// prep kernels
// ---------------------------------------------------------------------------
__global__ __launch_bounds__(256)
void wprep_kernel(const float* __restrict__ W, u16* __restrict__ out_hi,
                  u16* __restrict__ out_lo, int K, int Nw, int n_off, int out_ld)
{
    __shared__ float t[32][33];
    const int n0 = blockIdx.x * 32;
    const int k0 = blockIdx.y * 32;
    const int tx = threadIdx.x & 31;
    const int ty = threadIdx.x >> 5;
#pragma unroll
    for (int j = 0; j < 32; j += 8)
        t[ty + j][tx] = W[(size_t)(k0 + ty + j) * Nw + n0 + tx];
    __syncthreads();
#pragma unroll
    for (int j = 0; j < 32; j += 8) {
        float v = t[tx][ty + j];
        __nv_bfloat16 hb = __float2bfloat16(v);
        __nv_bfloat16 lb = __float2bfloat16(v - __bfloat162float(hb));
        size_t o = (size_t)(n_off + n0 + ty + j) * out_ld + k0 + tx;
        out_hi[o] = __bfloat16_as_ushort(hb);
        out_lo[o] = __bfloat16_as_ushort(lb);
    }
}

__global__ __launch_bounds__(256)
void xsplit_kernel(const float* __restrict__ x, u16* __restrict__ hi,
                   u16* __restrict__ lo, int n4)
{
    int i = blockIdx.x * 256 + threadIdx.x;
    if (i >= n4) return;
    float4 v = ((const float4*)x)[i];
    __nv_bfloat16 h0 = __float2bfloat16(v.x), h1 = __float2bfloat16(v.y);
    __nv_bfloat16 h2 = __float2bfloat16(v.z), h3 = __float2bfloat16(v.w);
    __nv_bfloat16 l0 = __float2bfloat16(v.x - __bfloat162float(h0));
    __nv_bfloat16 l1 = __float2bfloat16(v.y - __bfloat162float(h1));
    __nv_bfloat16 l2 = __float2bfloat16(v.z - __bfloat162float(h2));
    __nv_bfloat16 l3 = __float2bfloat16(v.w - __bfloat162float(h3));
    uint2 hv, lv;
    hv.x = (uint32_t)__bfloat16_as_ushort(h0) | ((uint32_t)__bfloat16_as_ushort(h1) << 16);
    hv.y = (uint32_t)__bfloat16_as_ushort(h2) | ((uint32_t)__bfloat16_as_ushort(h3) << 16);
    lv.x = (uint32_t)__bfloat16_as_ushort(l0) | ((uint32_t)__bfloat16_as_ushort(l1) << 16);
    lv.y = (uint32_t)__bfloat16_as_ushort(l2) | ((uint32_t)__bfloat16_as_ushort(l3) << 16);
    ((uint2*)hi)[i] = hv;
    ((uint2*)lo)[i] = lv;
}

__global__ void bias_cat_kernel(const float* __restrict__ ba, const float* __restrict__ bo,
                                const float* __restrict__ bB, const float* __restrict__ bdt)
{
    int n = blockIdx.x * 256 + threadIdx.x;
    if (n >= PRE_LD) return;
    float v;
    if (n < 1024)      v = ba[n];
    else if (n < 2048) v = bo[n - 1024];
    else if (n < 4096) v = bB[n - 2048];
    else               v = bdt[n - 4096];
    g_bias_cat[n] = v;
}

// ---------------------------------------------------------------------------
// HMMA GEMM: C[m, n] = sum_k A[m,k]*Bt[n,k] + bias[n]   (bf16x3, fp32 acc)
// A = Ah+Al, B = Bh+Bl; products hh + hl + lh.
// CTA 128x128, BK=64, 8 warps (warp tile 32x64), 3-stage cp.async ring.
// ---------------------------------------------------------------------------
__global__ __launch_bounds__(256)
void mma_gemm_kernel(const u16* __restrict__ Ah, const u16* __restrict__ Al,
                     const u16* __restrict__ Bh, const u16* __restrict__ Bl,
                     const float* __restrict__ bias, const float* __restrict__ xf32,
                     float* __restrict__ C, int K, int ldc, int do_xmul)
{
    extern __shared__ char smem[];
    const uint32_t sb = smem_u32(smem);
    const int tid = threadIdx.x;
    const int lane = tid & 31;
    const int warp = tid >> 5;
    const int wm = warp >> 1;         // 0..3
    const int wn = warp & 1;          // 0..1
    const int m0 = blockIdx.y * BM;
    const int n0 = blockIdx.x * BN;

    const u16* Abase_h = Ah + (size_t)m0 * K;
    const u16* Abase_l = Al + (size_t)m0 * K;
    const u16* Bbase_h = Bh + (size_t)n0 * K;
    const u16* Bbase_l = Bl + (size_t)n0 * K;

    const int S = K / BK;

    float acc[2][8][4];
#pragma unroll
    for (int i = 0; i < 2; i++)
#pragma unroll
        for (int j = 0; j < 8; j++)
#pragma unroll
            for (int q = 0; q < 4; q++) acc[i][j][q] = 0.f;

    // ---- stage loader (stage s -> buffer s % NSTAGE) ----
    auto load_stage = [&](int s) {
        const int kt = s * BK;
        const uint32_t buf = sb + (uint32_t)(s % NSTAGE) * STAGE_BYTES;
#pragma unroll
        for (int i = 0; i < 4; i++) {
            int id = tid + i * 256;          // 0..1023
            int r = id >> 3;                 // 0..127
            int c8 = (id & 7) * 8;           // 0..56
            uint32_t sw = swz((uint32_t)(r * 128 + c8 * 2));
            const size_t go = (size_t)r * K + kt + c8;
            CPASYNC16(buf + sw,         Abase_h + go);
            CPASYNC16(buf + 16384 + sw, Abase_l + go);
            CPASYNC16(buf + 32768 + sw, Bbase_h + go);
            CPASYNC16(buf + 49152 + sw, Bbase_l + go);
        }
        CPASYNC_COMMIT();
    };

    // prologue: fill 2 stages
    load_stage(0);
    load_stage(1);

    const int arow = wm * 32 + (lane & 15);
    const int brow = wn * 64 + (lane & 15);
    const int khb  = (lane >> 4) * 16;       // byte offset of k-half

    for (int s = 0; s < S; s++) {
        // stage s must be resident; stage s+1 may still be in flight
        if (s + 1 < S) { CPASYNC_WAIT1(); } else { CPASYNC_WAIT0(); }
        __syncthreads();   // also protects buffer (s+2)%3 == (s-1)%3 reuse below

        if (s + 2 < S) load_stage(s + 2);

        const uint32_t buf = sb + (uint32_t)(s % NSTAGE) * STAGE_BYTES;
#pragma unroll
        for (int kk = 0; kk < 4; kk++) {
            const uint32_t kb = (uint32_t)(kk * 32 + khb);
            uint32_t ah[2][4], al[2][4], bh[8][2], bl[8][2];
#pragma unroll
            for (int mi = 0; mi < 2; mi++) {
                uint32_t off = swz((uint32_t)((arow + mi * 16) * 128) + kb);
                ldsm_x4(ah[mi], buf + off);
                ldsm_x4(al[mi], buf + 16384 + off);
            }
#pragma unroll
            for (int g = 0; g < 4; g++) {
                uint32_t off = swz((uint32_t)((brow + g * 16) * 128) + kb);
                uint32_t t[4];
                ldsm_x4(t, buf + 32768 + off);
                bh[2 * g][0] = t[0]; bh[2 * g][1] = t[2];
                bh[2 * g + 1][0] = t[1]; bh[2 * g + 1][1] = t[3];
                ldsm_x4(t, buf + 49152 + off);
                bl[2 * g][0] = t[0]; bl[2 * g][1] = t[2];
                bl[2 * g + 1][0] = t[1]; bl[2 * g + 1][1] = t[3];
            }
#pragma unroll
            for (int mi = 0; mi < 2; mi++)
#pragma unroll
                for (int nj = 0; nj < 8; nj++) {
                    mma_bf16(acc[mi][nj], ah[mi], bh[nj]);
                    mma_bf16(acc[mi][nj], ah[mi], bl[nj]);
                    mma_bf16(acc[mi][nj], al[mi], bh[nj]);
                }
        }
    }
    __syncthreads();

    // ---- epilogue: direct stores with bias (+ optional x multiply) ----
    const int m0w = m0 + wm * 32;
    const int n0w = n0 + wn * 64;
#pragma unroll
    for (int mi = 0; mi < 2; mi++) {
        const int r0 = m0w + mi * 16 + (lane >> 2);
        const int r1 = r0 + 8;
#pragma unroll
        for (int nj = 0; nj < 8; nj++) {
            const int cn = n0w + nj * 8 + 2 * (lane & 3);
            float b0 = bias[cn], b1 = bias[cn + 1];
            float v0 = acc[mi][nj][0] + b0;
            float v1 = acc[mi][nj][1] + b1;
            float v2 = acc[mi][nj][2] + b0;
            float v3 = acc[mi][nj][3] + b1;
            if (do_xmul && cn >= 2048 && cn < 4096) {
                const int xc = (cn - 2048) >> 1;
                float xa = xf32[(size_t)r0 * DDIM + xc];
                float xb = xf32[(size_t)r1 * DDIM + xc];
                v0 *= xa; v1 *= xa; v2 *= xb; v3 *= xb;
            }
            float2 p0 = {v0, v1}, p1 = {v2, v3};
            *(float2*)(C + (size_t)r0 * ldc + cn) = p0;
            *(float2*)(C + (size_t)r1 * ldc + cn) = p1;
        }
    }
}

// ---------------------------------------------------------------------------
// Scan
// ---------------------------------------------------------------------------
__device__ __forceinline__ float softplusf(float v)
{
    return v > 20.f ? v : log1pf(expf(v));
}

struct StepAU { float ar, ai, u0, u1; };

__device__ __forceinline__ StepAU compute_step(const float* __restrict__ row, int d)
{
    float ap  = row[d];
    float om  = row[DDIM + d];
    float bx0 = row[2 * DDIM + 2 * d];
    float bx1 = row[2 * DDIM + 2 * d + 1];
    float dtp = row[4 * DDIM + d];

    float alpha = softplusf(ap);
    float dt    = softplusf(dtp);
    float tau = 0.5f * dt;
    float opa = fmaf(tau, alpha, 1.0f);
    float tw  = tau * om;
    float inv = 1.0f / fmaf(opa, opa, fmaf(tw, tw, 1e-6f));
    float m11 = opa * inv;
    float m12 = tw * inv;
    float oma = fmaf(-tau, alpha, 1.0f);

    StepAU r;
    r.ar = fmaf(m11, oma, -m12 * tw);
    float a12 = fmaf(m11, tw, m12 * oma);
    r.ai = -a12;
    r.u0 = dt * fmaf(m11, bx0, m12 * bx1);
    r.u1 = dt * fmaf(-m12, bx0, m11 * bx1);
    return r;
}

__global__ __launch_bounds__(256)
void scan_pass1()
{
    const int bid = blockIdx.x;
    const int d = (bid & 3) * 256 + threadIdx.x;
    const int c = (bid >> 2) & (NCH - 1);
    const int b = bid >> 8;

    float Pr = 1.f, Pi = 0.f, qr = 0.f, qi = 0.f;
    const size_t row0 = ((size_t)b * SDIM + (size_t)c * LCH);
#pragma unroll 4
    for (int i = 0; i < LCH; i++) {
        StepAU s = compute_step(g_pre + (row0 + i) * PRE_LD, d);
        float nPr = s.ar * Pr - s.ai * Pi;
        float nPi = s.ar * Pi + s.ai * Pr;
        float nqr = s.ar * qr - s.ai * qi + s.u0;
        float nqi = s.ar * qi + s.ai * qr + s.u1;
        Pr = nPr; Pi = nPi; qr = nqr; qi = nqi;
    }
    const size_t o = (((size_t)b * NCH + c) * 2) * DDIM + d;
    g_P[o] = Pr; g_P[o + DDIM] = Pi;
    g_Q[o] = qr; g_Q[o + DDIM] = qi;
}

__global__ __launch_bounds__(256)
void scan_pass2(const float* __restrict__ state, float* __restrict__ fs)
{
    const int b = blockIdx.x >> 2;
    const int d = (blockIdx.x & 3) * 256 + threadIdx.x;

    float hr = state[((size_t)b * DDIM + d) * 2 + 0];
    float hi = state[((size_t)b * DDIM + d) * 2 + 1];
#pragma unroll 4
    for (int c = 0; c < NCH; c++) {
        const size_t o = (((size_t)b * NCH + c) * 2) * DDIM + d;
        g_h0[o] = hr; g_h0[o + DDIM] = hi;
        float Pr = g_P[o], Pi = g_P[o + DDIM];
        float qr = g_Q[o], qi = g_Q[o + DDIM];
        float nr = Pr * hr - Pi * hi + qr;
        float ni = Pr * hi + Pi * hr + qi;
        hr = nr; hi = ni;
    }
    if (fs) {
        fs[((size_t)b * DDIM + d) * 2 + 0] = hr;
        fs[((size_t)b * DDIM + d) * 2 + 1] = hi;
    }
}

// pass 3: regenerate per-step states, emit as bf16 hi/lo (A operand of GEMM2)
__global__ __launch_bounds__(256)
void scan_pass3()
{
    const int bid = blockIdx.x;
    const int d = (bid & 3) * 256 + threadIdx.x;
    const int c = (bid >> 2) & (NCH - 1);
    const int b = bid >> 8;

    const size_t o = (((size_t)b * NCH + c) * 2) * DDIM + d;
    float hr = g_h0[o], hi = g_h0[o + DDIM];
    const size_t row0 = ((size_t)b * SDIM + (size_t)c * LCH);
#pragma unroll 4
    for (int i = 0; i < LCH; i++) {
        StepAU s = compute_step(g_pre + (row0 + i) * PRE_LD, d);
        float nr = s.ar * hr - s.ai * hi + s.u0;
        float ni = s.ar * hi + s.ai * hr + s.u1;
        hr = nr; hi = ni;
        __nv_bfloat16 hh = __float2bfloat16(hr);
        __nv_bfloat16 ih = __float2bfloat16(hi);
        __nv_bfloat16 hl = __float2bfloat16(hr - __bfloat162float(hh));
        __nv_bfloat16 il = __float2bfloat16(hi - __bfloat162float(ih));
        uint32_t hp = (uint32_t)__bfloat16_as_ushort(hh) | ((uint32_t)__bfloat16_as_ushort(ih) << 16);
        uint32_t lp = (uint32_t)__bfloat16_as_ushort(hl) | ((uint32_t)__bfloat16_as_ushort(il) << 16);
        ((uint32_t*)g_sth)[(row0 + i) * DDIM + d] = hp;
        ((uint32_t*)g_stl)[(row0 + i) * DDIM + d] = lp;
    }
}

// ---------------------------------------------------------------------------
// launch
// ---------------------------------------------------------------------------
extern "C" void kernel_launch(void* const* d_in, const int* in_sizes, int n_in,
                              void* d_out, int out_size)
{
    const float* x     = (const float*)d_in[0];
    const float* state = (const float*)d_in[1];
    const float* Wa    = (const float*)d_in[2];
    const float* ba    = (const float*)d_in[3];
    const float* Wo    = (const float*)d_in[4];
    const float* bo    = (const float*)d_in[5];
    const float* WB    = (const float*)d_in[6];
    const float* bB    = (const float*)d_in[7];
    const float* Wdt   = (const float*)d_in[8];
    const float *bdt, *WC, *bC;
    if (n_in >= 12 && in_sizes[9] == 1024) {
        bdt = (const float*)d_in[9];
        WC  = (const float*)d_in[10];
        bC  = (const float*)d_in[11];
    } else {
        WC  = (const float*)d_in[9];
        bC  = (const float*)d_in[10];
        bdt = (const float*)d_in[11];
    }
    float* out = (float*)d_out;

    float* pre = nullptr;
    u16 *wth, *wtl, *wcth, *wctl, *xh, *xl, *sth, *stl;
    cudaGetSymbolAddress((void**)&pre, g_pre);
    cudaGetSymbolAddress((void**)&wth, g_Wt_hi);
    cudaGetSymbolAddress((void**)&wtl, g_Wt_lo);
    cudaGetSymbolAddress((void**)&wcth, g_WCt_hi);
    cudaGetSymbolAddress((void**)&wctl, g_WCt_lo);
    cudaGetSymbolAddress((void**)&xh, g_xh);
    cudaGetSymbolAddress((void**)&xl, g_xl);
    cudaGetSymbolAddress((void**)&sth, g_sth);
    cudaGetSymbolAddress((void**)&stl, g_stl);
    float* bias_cat = nullptr;
    cudaGetSymbolAddress((void**)&bias_cat, g_bias_cat);

    float* fs = (out_size >= MDIM * DDIM + BDIM * DDIM * 2)
                ? out + (size_t)MDIM * DDIM : nullptr;

    cudaFuncSetAttribute(mma_gemm_kernel, cudaFuncAttributeMaxDynamicSharedMemorySize, SM_TOTAL);

    const dim3 t(256);
    // prep: weight transpose + split, x split, bias concat
    wprep_kernel<<<dim3(32, 32), t>>>(Wa,  wth, wtl, DDIM, DDIM,     0,    DDIM);
    wprep_kernel<<<dim3(32, 32), t>>>(Wo,  wth, wtl, DDIM, DDIM,     1024, DDIM);
    wprep_kernel<<<dim3(64, 32), t>>>(WB,  wth, wtl, DDIM, 2 * DDIM, 2048, DDIM);
    wprep_kernel<<<dim3(32, 32), t>>>(Wdt, wth, wtl, DDIM, DDIM,     4096, DDIM);
    wprep_kernel<<<dim3(32, 64), t>>>(WC,  wcth, wctl, 2 * DDIM, DDIM, 0, 2 * DDIM);
    xsplit_kernel<<<(MDIM * DDIM / 4 + 255) / 256, t>>>(x, xh, xl, MDIM * DDIM / 4);
    bias_cat_kernel<<<20, 256>>>(ba, bo, bB, bdt);

    // pre-activation GEMM (M=16384, N=5120, K=1024)
    mma_gemm_kernel<<<dim3(PRE_LD / BN, MDIM / BM), t, SM_TOTAL>>>(
        xh, xl, wth, wtl, bias_cat, x, pre, DDIM, PRE_LD, 1);

    // chunked scan
    scan_pass1<<<BDIM * NCH * (DDIM / 256), t>>>();
    scan_pass2<<<BDIM * (DDIM / 256), t>>>(state, fs);
    scan_pass3<<<BDIM * NCH * (DDIM / 256), t>>>();

    // output GEMM (M=16384, N=1024, K=2048)
    mma_gemm_kernel<<<dim3(DDIM / BN, MDIM / BM), t, SM_TOTAL>>>(
        sth, stl, wcth, wctl, bC, nullptr, out, 2 * DDIM, DDIM, 0);
}

// round 6
// speedup vs baseline: 1.0863x; 1.0863x over previous
#include <cuda_runtime.h>
#include <cuda_bf16.h>
#include <cstdint>
#include <cstddef>

// ---------------------------------------------------------------------------
// KSSM layer: B=4, S=4096, D=1024
// GEMMs: bf16x3 (hi/lo split) on mma.sync HMMA, BK=32 / 3-stage / 96KB smem
// so 2 CTAs co-reside per SM. Scan: chunked complex scan.
// ---------------------------------------------------------------------------

#define BDIM 4
#define SDIM 4096
#define DDIM 1024
#define MDIM (BDIM * SDIM)        // 16384
#define PRE_LD 5120               // [alpha | omega | Bx(interleaved) | dt]
#define NCH 64
#define LCH 64

// GEMM tiling
#define BM 128
#define BN 128
#define BK 32
#define NSTAGE 3
#define TILE_BYTES 8192           // 128 x 32 x 2B
#define STAGE_BYTES (4 * TILE_BYTES)
#define SM_TOTAL (NSTAGE * STAGE_BYTES)   // 96KB -> 2 CTAs/SM

typedef unsigned short u16;

// scratch (static device memory)
__device__ __align__(256) float g_pre[(size_t)MDIM * PRE_LD];
__device__ __align__(256) float g_P[(size_t)BDIM * NCH * 2 * DDIM];
__device__ __align__(256) float g_Q[(size_t)BDIM * NCH * 2 * DDIM];
__device__ __align__(256) float g_h0[(size_t)BDIM * NCH * 2 * DDIM];
__device__ __align__(256) u16 g_xh[(size_t)MDIM * DDIM];
__device__ __align__(256) u16 g_xl[(size_t)MDIM * DDIM];
__device__ __align__(256) u16 g_sth[(size_t)MDIM * 2 * DDIM];
__device__ __align__(256) u16 g_stl[(size_t)MDIM * 2 * DDIM];
__device__ __align__(256) u16 g_Wt_hi[(size_t)PRE_LD * DDIM];    // [n][k]
__device__ __align__(256) u16 g_Wt_lo[(size_t)PRE_LD * DDIM];
__device__ __align__(256) u16 g_WCt_hi[(size_t)DDIM * 2 * DDIM]; // [n][k=2048]
__device__ __align__(256) u16 g_WCt_lo[(size_t)DDIM * 2 * DDIM];
__device__ __align__(256) float g_bias_cat[PRE_LD];

// ---------------------------------------------------------------------------
// helpers
// ---------------------------------------------------------------------------
__device__ __forceinline__ uint32_t smem_u32(const void* p) {
    uint32_t a;
    asm("{ .reg .u64 t; cvta.to.shared.u64 t, %1; cvt.u32.u64 %0, t; }" : "=r"(a) : "l"(p));
    return a;
}

// SW64 swizzle for 64-byte rows: bits[5:4] ^= bits[8:7]
__device__ __forceinline__ uint32_t swz64(uint32_t o) { return o ^ ((o >> 3) & 0x30); }

#define CPASYNC16(dst, src) \
    asm volatile("cp.async.cg.shared.global [%0], [%1], 16;" :: "r"(dst), "l"(src))
#define CPASYNC_COMMIT() asm volatile("cp.async.commit_group;" ::: "memory")
#define CPASYNC_WAIT1()  asm volatile("cp.async.wait_group 1;" ::: "memory")
#define CPASYNC_WAIT0()  asm volatile("cp.async.wait_group 0;" ::: "memory")

__device__ __forceinline__ void ldsm_x4(uint32_t* r, uint32_t addr) {
    asm volatile("ldmatrix.sync.aligned.m8n8.x4.shared.b16 {%0,%1,%2,%3}, [%4];"
                 : "=r"(r[0]), "=r"(r[1]), "=r"(r[2]), "=r"(r[3]) : "r"(addr));
}

__device__ __forceinline__ void mma_bf16(float* c, const uint32_t* a, const uint32_t* b) {
    asm volatile(
        "mma.sync.aligned.m16n8k16.row.col.f32.bf16.bf16.f32 "
        "{%0,%1,%2,%3}, {%4,%5,%6,%7}, {%8,%9}, {%0,%1,%2,%3};"
        : "+f"(c[0]), "+f"(c[1]), "+f"(c[2]), "+f"(c[3])
        : "r"(a[0]), "r"(a[1]), "r"(a[2]), "r"(a[3]), "r"(b[0]), "r"(b[1]));
}

// ---------------------------------------------------------------------------
// prep kernels
// ---------------------------------------------------------------------------
__device__ __forceinline__ void wprep_body(const float* __restrict__ W, int Nw,
                                           int n0, int n_off, int k0,
                                           u16* __restrict__ out_hi, u16* __restrict__ out_lo,
                                           int out_ld, int tx, int ty, float (*t)[33])
{
#pragma unroll
    for (int j = 0; j < 32; j += 8)
        t[ty + j][tx] = W[(size_t)(k0 + ty + j) * Nw + n0 + tx];
    __syncthreads();
#pragma unroll
    for (int j = 0; j < 32; j += 8) {
        float v = t[tx][ty + j];
        __nv_bfloat16 hb = __float2bfloat16(v);
        __nv_bfloat16 lb = __float2bfloat16(v - __bfloat162float(hb));
        size_t o = (size_t)(n_off + n0 + ty + j) * out_ld + k0 + tx;
        out_hi[o] = __bfloat16_as_ushort(hb);
        out_lo[o] = __bfloat16_as_ushort(lb);
    }
}

// z selects: 0=Wa, 1=Wo, 2=WB[0:1024), 3=WB[1024:2048), 4=Wdt
__global__ __launch_bounds__(256)
void wprep_all_kernel(const float* __restrict__ Wa, const float* __restrict__ Wo,
                      const float* __restrict__ WB, const float* __restrict__ Wdt)
{
    __shared__ float t[32][33];
    const int tx = threadIdx.x & 31;
    const int ty = threadIdx.x >> 5;
    const int k0 = blockIdx.y * 32;
    const int z = blockIdx.z;
    const float* W;
    int Nw, n0 = blockIdx.x * 32, n_off;
    if (z == 0)      { W = Wa;  Nw = 1024; n_off = 0; }
    else if (z == 1) { W = Wo;  Nw = 1024; n_off = 1024; }
    else if (z == 2) { W = WB;  Nw = 2048; n_off = 2048; }
    else if (z == 3) { W = WB;  Nw = 2048; n_off = 2048; n0 += 1024; }
    else             { W = Wdt; Nw = 1024; n_off = 4096; }
    wprep_body(W, Nw, n0, n_off, k0, g_Wt_hi, g_Wt_lo, DDIM, tx, ty, t);
}

__global__ __launch_bounds__(256)
void wprep_wc_kernel(const float* __restrict__ WC)
{
    __shared__ float t[32][33];
    const int tx = threadIdx.x & 31;
    const int ty = threadIdx.x >> 5;
    wprep_body(WC, DDIM, blockIdx.x * 32, 0, blockIdx.y * 32,
               g_WCt_hi, g_WCt_lo, 2 * DDIM, tx, ty, t);
}

#define XSPLIT_BLOCKS (MDIM * DDIM / 4 / 256)   // 16384
__global__ __launch_bounds__(256)
void xsplit_bias_kernel(const float* __restrict__ x,
                        const float* __restrict__ ba, const float* __restrict__ bo,
                        const float* __restrict__ bB, const float* __restrict__ bdt)
{
    if (blockIdx.x >= XSPLIT_BLOCKS) {
        int n = (blockIdx.x - XSPLIT_BLOCKS) * 256 + threadIdx.x;
        if (n >= PRE_LD) return;
        float v;
        if (n < 1024)      v = ba[n];
        else if (n < 2048) v = bo[n - 1024];
        else if (n < 4096) v = bB[n - 2048];
        else               v = bdt[n - 4096];
        g_bias_cat[n] = v;
        return;
    }
    int i = blockIdx.x * 256 + threadIdx.x;
    float4 v = ((const float4*)x)[i];
    __nv_bfloat16 h0 = __float2bfloat16(v.x), h1 = __float2bfloat16(v.y);
    __nv_bfloat16 h2 = __float2bfloat16(v.z), h3 = __float2bfloat16(v.w);
    __nv_bfloat16 l0 = __float2bfloat16(v.x - __bfloat162float(h0));
    __nv_bfloat16 l1 = __float2bfloat16(v.y - __bfloat162float(h1));
    __nv_bfloat16 l2 = __float2bfloat16(v.z - __bfloat162float(h2));
    __nv_bfloat16 l3 = __float2bfloat16(v.w - __bfloat162float(h3));
    uint2 hv, lv;
    hv.x = (uint32_t)__bfloat16_as_ushort(h0) | ((uint32_t)__bfloat16_as_ushort(h1) << 16);
    hv.y = (uint32_t)__bfloat16_as_ushort(h2) | ((uint32_t)__bfloat16_as_ushort(h3) << 16);
    lv.x = (uint32_t)__bfloat16_as_ushort(l0) | ((uint32_t)__bfloat16_as_ushort(l1) << 16);
    lv.y = (uint32_t)__bfloat16_as_ushort(l2) | ((uint32_t)__bfloat16_as_ushort(l3) << 16);
    ((uint2*)g_xh)[i] = hv;
    ((uint2*)g_xl)[i] = lv;
}

__global__ void dummy_kernel() {}

// ---------------------------------------------------------------------------
// HMMA GEMM: C[m, n] = sum_k A[m,k]*Bt[n,k] + bias[n]   (bf16x3, fp32 acc)
// CTA 128x128, BK=32, 8 warps (warp tile 32x64), 3-stage ring, 2 CTAs/SM.
// ---------------------------------------------------------------------------
__global__ __launch_bounds__(256, 2)
void mma_gemm_kernel(const u16* __restrict__ Ah, const u16* __restrict__ Al,
                     const u16* __restrict__ Bh, const u16* __restrict__ Bl,
                     const float* __restrict__ bias, const float* __restrict__ xf32,
                     float* __restrict__ C, int K, int ldc, int do_xmul)
{
    extern __shared__ char smem[];
    const uint32_t sb = smem_u32(smem);
    const int tid = threadIdx.x;
    const int lane = tid & 31;
    const int warp = tid >> 5;
    const int wm = warp >> 1;         // 0..3
    const int wn = warp & 1;          // 0..1
    const int m0 = blockIdx.y * BM;
    const int n0 = blockIdx.x * BN;

    const u16* Abase_h = Ah + (size_t)m0 * K;
    const u16* Abase_l = Al + (size_t)m0 * K;
    const u16* Bbase_h = Bh + (size_t)n0 * K;
    const u16* Bbase_l = Bl + (size_t)n0 * K;

    const int S = K / BK;

    float acc[2][8][4];
#pragma unroll
    for (int i = 0; i < 2; i++)
#pragma unroll
        for (int j = 0; j < 8; j++)
#pragma unroll
            for (int q = 0; q < 4; q++) acc[i][j][q] = 0.f;

    // ---- stage loader: 4 tiles of 128x32 (64B rows, SW64 swizzle) ----
    auto load_stage = [&](int s) {
        const int kt = s * BK;
        const uint32_t buf = sb + (uint32_t)(s % NSTAGE) * STAGE_BYTES;
        const u16* bases[4] = {Abase_h, Abase_l, Bbase_h, Bbase_l};
#pragma unroll
        for (int t = 0; t < 4; t++) {
            const u16* base = bases[t];
            const uint32_t tb = buf + t * TILE_BYTES;
#pragma unroll
            for (int i = 0; i < 2; i++) {
                int id = tid + i * 256;        // 0..511
                int r = id >> 2;               // 0..127
                int c = id & 3;                // 16B chunk
                uint32_t sw = swz64((uint32_t)(r * 64 + c * 16));
                CPASYNC16(tb + sw, base + (size_t)r * K + kt + c * 8);
            }
        }
        CPASYNC_COMMIT();
    };

    // prologue: fill 2 stages
    load_stage(0);
    load_stage(1);

    const int arow = wm * 32 + (lane & 15);
    const int brow = wn * 64 + (lane & 15);
    const int khb  = (lane >> 4) * 16;       // byte offset of k-half

    for (int s = 0; s < S; s++) {
        if (s + 1 < S) { CPASYNC_WAIT1(); } else { CPASYNC_WAIT0(); }
        __syncthreads();   // also protects ring buffer reuse

        if (s + 2 < S) load_stage(s + 2);

        const uint32_t buf = sb + (uint32_t)(s % NSTAGE) * STAGE_BYTES;
#pragma unroll
        for (int kk = 0; kk < 2; kk++) {
            const uint32_t kb = (uint32_t)(kk * 32 + khb);
            uint32_t ah[2][4], al[2][4];
#pragma unroll
            for (int mi = 0; mi < 2; mi++) {
                uint32_t off = swz64((uint32_t)((arow + mi * 16) * 64) + kb);
                ldsm_x4(ah[mi], buf + off);
                ldsm_x4(al[mi], buf + TILE_BYTES + off);
            }
#pragma unroll
            for (int g = 0; g < 4; g++) {
                uint32_t off = swz64((uint32_t)((brow + g * 16) * 64) + kb);
                uint32_t th[4], tl[4];
                ldsm_x4(th, buf + 2 * TILE_BYTES + off);
                ldsm_x4(tl, buf + 3 * TILE_BYTES + off);
                uint32_t b0h[2] = {th[0], th[2]}, b1h[2] = {th[1], th[3]};
                uint32_t b0l[2] = {tl[0], tl[2]}, b1l[2] = {tl[1], tl[3]};
#pragma unroll
                for (int mi = 0; mi < 2; mi++) {
                    mma_bf16(acc[mi][2 * g],     ah[mi], b0h);
                    mma_bf16(acc[mi][2 * g],     ah[mi], b0l);
                    mma_bf16(acc[mi][2 * g],     al[mi], b0h);
                    mma_bf16(acc[mi][2 * g + 1], ah[mi], b1h);
                    mma_bf16(acc[mi][2 * g + 1], ah[mi], b1l);
                    mma_bf16(acc[mi][2 * g + 1], al[mi], b1h);
                }
            }
        }
    }
    __syncthreads();

    // ---- epilogue: direct stores with bias (+ optional x multiply) ----
    const int m0w = m0 + wm * 32;
    const int n0w = n0 + wn * 64;
#pragma unroll
    for (int mi = 0; mi < 2; mi++) {
        const int r0 = m0w + mi * 16 + (lane >> 2);
        const int r1 = r0 + 8;
#pragma unroll
        for (int nj = 0; nj < 8; nj++) {
            const int cn = n0w + nj * 8 + 2 * (lane & 3);
            float b0 = bias[cn], b1 = bias[cn + 1];
            float v0 = acc[mi][nj][0] + b0;
            float v1 = acc[mi][nj][1] + b1;
            float v2 = acc[mi][nj][2] + b0;
            float v3 = acc[mi][nj][3] + b1;
            if (do_xmul && cn >= 2048 && cn < 4096) {
                const int xc = (cn - 2048) >> 1;
                float xa = xf32[(size_t)r0 * DDIM + xc];
                float xb = xf32[(size_t)r1 * DDIM + xc];
                v0 *= xa; v1 *= xa; v2 *= xb; v3 *= xb;
            }
            float2 p0 = {v0, v1}, p1 = {v2, v3};
            *(float2*)(C + (size_t)r0 * ldc + cn) = p0;
            *(float2*)(C + (size_t)r1 * ldc + cn) = p1;
        }
    }
}

// ---------------------------------------------------------------------------
// Scan
// ---------------------------------------------------------------------------
__device__ __forceinline__ float softplusf(float v)
{
    return v > 20.f ? v : log1pf(expf(v));
}

struct StepAU { float ar, ai, u0, u1; };

__device__ __forceinline__ StepAU compute_step(const float* __restrict__ row, int d)
{
    float ap  = row[d];
    float om  = row[DDIM + d];
    float bx0 = row[2 * DDIM + 2 * d];
    float bx1 = row[2 * DDIM + 2 * d + 1];
    float dtp = row[4 * DDIM + d];

    float alpha = softplusf(ap);
    float dt    = softplusf(dtp);
    float tau = 0.5f * dt;
    float opa = fmaf(tau, alpha, 1.0f);
    float tw  = tau * om;
    float inv = 1.0f / fmaf(opa, opa, fmaf(tw, tw, 1e-6f));
    float m11 = opa * inv;
    float m12 = tw * inv;
    float oma = fmaf(-tau, alpha, 1.0f);

    StepAU r;
    r.ar = fmaf(m11, oma, -m12 * tw);
    float a12 = fmaf(m11, tw, m12 * oma);
    r.ai = -a12;
    r.u0 = dt * fmaf(m11, bx0, m12 * bx1);
    r.u1 = dt * fmaf(-m12, bx0, m11 * bx1);
    return r;
}

__global__ __launch_bounds__(256)
void scan_pass1()
{
    const int bid = blockIdx.x;
    const int d = (bid & 3) * 256 + threadIdx.x;
    const int c = (bid >> 2) & (NCH - 1);
    const int b = bid >> 8;

    float Pr = 1.f, Pi = 0.f, qr = 0.f, qi = 0.f;
    const size_t row0 = ((size_t)b * SDIM + (size_t)c * LCH);
#pragma unroll 4
    for (int i = 0; i < LCH; i++) {
        StepAU s = compute_step(g_pre + (row0 + i) * PRE_LD, d);
        float nPr = s.ar * Pr - s.ai * Pi;
        float nPi = s.ar * Pi + s.ai * Pr;
        float nqr = s.ar * qr - s.ai * qi + s.u0;
        float nqi = s.ar * qi + s.ai * qr + s.u1;
        Pr = nPr; Pi = nPi; qr = nqr; qi = nqi;
    }
    const size_t o = (((size_t)b * NCH + c) * 2) * DDIM + d;
    g_P[o] = Pr; g_P[o + DDIM] = Pi;
    g_Q[o] = qr; g_Q[o + DDIM] = qi;
}

__global__ __launch_bounds__(256)
void scan_pass2(const float* __restrict__ state, float* __restrict__ fs)
{
    const int b = blockIdx.x >> 2;
    const int d = (blockIdx.x & 3) * 256 + threadIdx.x;

    float hr = state[((size_t)b * DDIM + d) * 2 + 0];
    float hi = state[((size_t)b * DDIM + d) * 2 + 1];
#pragma unroll 4
    for (int c = 0; c < NCH; c++) {
        const size_t o = (((size_t)b * NCH + c) * 2) * DDIM + d;
        g_h0[o] = hr; g_h0[o + DDIM] = hi;
        float Pr = g_P[o], Pi = g_P[o + DDIM];
        float qr = g_Q[o], qi = g_Q[o + DDIM];
        float nr = Pr * hr - Pi * hi + qr;
        float ni = Pr * hi + Pi * hr + qi;
        hr = nr; hi = ni;
    }
    if (fs) {
        fs[((size_t)b * DDIM + d) * 2 + 0] = hr;
        fs[((size_t)b * DDIM + d) * 2 + 1] = hi;
    }
}

// pass 3: regenerate per-step states, emit as bf16 hi/lo (A operand of GEMM2)
__global__ __launch_bounds__(256)
void scan_pass3()
{
    const int bid = blockIdx.x;
    const int d = (bid & 3) * 256 + threadIdx.x;
    const int c = (bid >> 2) & (NCH - 1);
    const int b = bid >> 8;

    const size_t o = (((size_t)b * NCH + c) * 2) * DDIM + d;
    float hr = g_h0[o], hi = g_h0[o + DDIM];
    const size_t row0 = ((size_t)b * SDIM + (size_t)c * LCH);
#pragma unroll 4
    for (int i = 0; i < LCH; i++) {
        StepAU s = compute_step(g_pre + (row0 + i) * PRE_LD, d);
        float nr = s.ar * hr - s.ai * hi + s.u0;
        float ni = s.ar * hi + s.ai * hr + s.u1;
        hr = nr; hi = ni;
        __nv_bfloat16 hh = __float2bfloat16(hr);
        __nv_bfloat16 ih = __float2bfloat16(hi);
        __nv_bfloat16 hl = __float2bfloat16(hr - __bfloat162float(hh));
        __nv_bfloat16 il = __float2bfloat16(hi - __bfloat162float(ih));
        uint32_t hp = (uint32_t)__bfloat16_as_ushort(hh) | ((uint32_t)__bfloat16_as_ushort(ih) << 16);
        uint32_t lp = (uint32_t)__bfloat16_as_ushort(hl) | ((uint32_t)__bfloat16_as_ushort(il) << 16);
        ((uint32_t*)g_sth)[(row0 + i) * DDIM + d] = hp;
        ((uint32_t*)g_stl)[(row0 + i) * DDIM + d] = lp;
    }
}

// ---------------------------------------------------------------------------
// launch
// ---------------------------------------------------------------------------
extern "C" void kernel_launch(void* const* d_in, const int* in_sizes, int n_in,
                              void* d_out, int out_size)
{
    const float* x     = (const float*)d_in[0];
    const float* state = (const float*)d_in[1];
    const float* Wa    = (const float*)d_in[2];
    const float* ba    = (const float*)d_in[3];
    const float* Wo    = (const float*)d_in[4];
    const float* bo    = (const float*)d_in[5];
    const float* WB    = (const float*)d_in[6];
    const float* bB    = (const float*)d_in[7];
    const float* Wdt   = (const float*)d_in[8];
    const float *bdt, *WC, *bC;
    if (n_in >= 12 && in_sizes[9] == 1024) {
        bdt = (const float*)d_in[9];
        WC  = (const float*)d_in[10];
        bC  = (const float*)d_in[11];
    } else {
        WC  = (const float*)d_in[9];
        bC  = (const float*)d_in[10];
        bdt = (const float*)d_in[11];
    }
    float* out = (float*)d_out;

    float* pre = nullptr;
    u16 *wth, *wtl, *wcth, *wctl, *xh, *xl, *sth, *stl;
    cudaGetSymbolAddress((void**)&pre, g_pre);
    cudaGetSymbolAddress((void**)&wth, g_Wt_hi);
    cudaGetSymbolAddress((void**)&wtl, g_Wt_lo);
    cudaGetSymbolAddress((void**)&wcth, g_WCt_hi);
    cudaGetSymbolAddress((void**)&wctl, g_WCt_lo);
    cudaGetSymbolAddress((void**)&xh, g_xh);
    cudaGetSymbolAddress((void**)&xl, g_xl);
    cudaGetSymbolAddress((void**)&sth, g_sth);
    cudaGetSymbolAddress((void**)&stl, g_stl);
    float* bias_cat = nullptr;
    cudaGetSymbolAddress((void**)&bias_cat, g_bias_cat);

    float* fs = (out_size >= MDIM * DDIM + BDIM * DDIM * 2)
                ? out + (size_t)MDIM * DDIM : nullptr;

    cudaFuncSetAttribute(mma_gemm_kernel, cudaFuncAttributeMaxDynamicSharedMemorySize, SM_TOTAL);

    const dim3 t(256);
    // launches 1-4 (prep); gemm1 is launch #5 so ncu -s 5 lands on it (or scan1)
    wprep_all_kernel<<<dim3(32, 32, 5), t>>>(Wa, Wo, WB, Wdt);          // 1
    wprep_wc_kernel<<<dim3(32, 64), t>>>(WC);                           // 2
    xsplit_bias_kernel<<<XSPLIT_BLOCKS + 20, t>>>(x, ba, bo, bB, bdt);  // 3
    dummy_kernel<<<1, 32>>>();                                          // 4

    // pre-activation GEMM (M=16384, N=5120, K=1024)                    // 5
    mma_gemm_kernel<<<dim3(PRE_LD / BN, MDIM / BM), t, SM_TOTAL>>>(
        xh, xl, wth, wtl, bias_cat, x, pre, DDIM, PRE_LD, 1);

    // chunked scan                                                     // 6,7,8
    scan_pass1<<<BDIM * NCH * (DDIM / 256), t>>>();
    scan_pass2<<<BDIM * (DDIM / 256), t>>>(state, fs);
    scan_pass3<<<BDIM * NCH * (DDIM / 256), t>>>();

    // output GEMM (M=16384, N=1024, K=2048)                            // 9
    mma_gemm_kernel<<<dim3(DDIM / BN, MDIM / BM), t, SM_TOTAL>>>(
        sth, stl, wcth, wctl, bC, nullptr, out, 2 * DDIM, DDIM, 0);
}

// round 7
// speedup vs baseline: 1.1056x; 1.0178x over previous
#include <cuda_runtime.h>
#include <cuda_bf16.h>
#include <cstdint>
#include <cstddef>

// ---------------------------------------------------------------------------
// KSSM layer: B=4, S=4096, D=1024
// GEMMs: bf16x3 (hi/lo split) on mma.sync HMMA, BK=32 / 3-stage / 96KB smem,
// 2 CTAs/SM; MMA issue order de-chained (no same-acc back-to-back HMMAs).
// ---------------------------------------------------------------------------

#define BDIM 4
#define SDIM 4096
#define DDIM 1024
#define MDIM (BDIM * SDIM)        // 16384
#define PRE_LD 5120               // [alpha | omega | Bx(interleaved) | dt]
#define NCH 64
#define LCH 64

// GEMM tiling
#define BM 128
#define BN 128
#define BK 32
#define NSTAGE 3
#define TILE_BYTES 8192           // 128 x 32 x 2B
#define STAGE_BYTES (4 * TILE_BYTES)
#define SM_TOTAL (NSTAGE * STAGE_BYTES)   // 96KB -> 2 CTAs/SM

typedef unsigned short u16;

// scratch (static device memory)
__device__ __align__(256) float g_pre[(size_t)MDIM * PRE_LD];
__device__ __align__(256) float g_P[(size_t)BDIM * NCH * 2 * DDIM];
__device__ __align__(256) float g_Q[(size_t)BDIM * NCH * 2 * DDIM];
__device__ __align__(256) float g_h0[(size_t)BDIM * NCH * 2 * DDIM];
__device__ __align__(256) u16 g_xh[(size_t)MDIM * DDIM];
__device__ __align__(256) u16 g_xl[(size_t)MDIM * DDIM];
__device__ __align__(256) u16 g_sth[(size_t)MDIM * 2 * DDIM];
__device__ __align__(256) u16 g_stl[(size_t)MDIM * 2 * DDIM];
__device__ __align__(256) u16 g_Wt_hi[(size_t)PRE_LD * DDIM];    // [n][k]
__device__ __align__(256) u16 g_Wt_lo[(size_t)PRE_LD * DDIM];
__device__ __align__(256) u16 g_WCt_hi[(size_t)DDIM * 2 * DDIM]; // [n][k=2048]
__device__ __align__(256) u16 g_WCt_lo[(size_t)DDIM * 2 * DDIM];
__device__ __align__(256) float g_bias_cat[PRE_LD];

// ---------------------------------------------------------------------------
// helpers
// ---------------------------------------------------------------------------
__device__ __forceinline__ uint32_t smem_u32(const void* p) {
    uint32_t a;
    asm("{ .reg .u64 t; cvta.to.shared.u64 t, %1; cvt.u32.u64 %0, t; }" : "=r"(a) : "l"(p));
    return a;
}

// SW64 swizzle for 64-byte rows: bits[5:4] ^= bits[8:7]
__device__ __forceinline__ uint32_t swz64(uint32_t o) { return o ^ ((o >> 3) & 0x30); }

#define CPASYNC16(dst, src) \
    asm volatile("cp.async.cg.shared.global [%0], [%1], 16;" :: "r"(dst), "l"(src))
#define CPASYNC_COMMIT() asm volatile("cp.async.commit_group;" ::: "memory")
#define CPASYNC_WAIT1()  asm volatile("cp.async.wait_group 1;" ::: "memory")
#define CPASYNC_WAIT0()  asm volatile("cp.async.wait_group 0;" ::: "memory")

__device__ __forceinline__ void ldsm_x4(uint32_t* r, uint32_t addr) {
    asm volatile("ldmatrix.sync.aligned.m8n8.x4.shared.b16 {%0,%1,%2,%3}, [%4];"
                 : "=r"(r[0]), "=r"(r[1]), "=r"(r[2]), "=r"(r[3]) : "r"(addr));
}

__device__ __forceinline__ void mma_bf16(float* c, const uint32_t* a, const uint32_t* b) {
    asm volatile(
        "mma.sync.aligned.m16n8k16.row.col.f32.bf16.bf16.f32 "
        "{%0,%1,%2,%3}, {%4,%5,%6,%7}, {%8,%9}, {%0,%1,%2,%3};"
        : "+f"(c[0]), "+f"(c[1]), "+f"(c[2]), "+f"(c[3])
        : "r"(a[0]), "r"(a[1]), "r"(a[2]), "r"(a[3]), "r"(b[0]), "r"(b[1]));
}

// ---------------------------------------------------------------------------
// prep kernels
// ---------------------------------------------------------------------------
__device__ __forceinline__ void wprep_body(const float* __restrict__ W, int Nw,
                                           int n0, int n_off, int k0,
                                           u16* __restrict__ out_hi, u16* __restrict__ out_lo,
                                           int out_ld, int tx, int ty, float (*t)[33])
{
#pragma unroll
    for (int j = 0; j < 32; j += 8)
        t[ty + j][tx] = W[(size_t)(k0 + ty + j) * Nw + n0 + tx];
    __syncthreads();
#pragma unroll
    for (int j = 0; j < 32; j += 8) {
        float v = t[tx][ty + j];
        __nv_bfloat16 hb = __float2bfloat16(v);
        __nv_bfloat16 lb = __float2bfloat16(v - __bfloat162float(hb));
        size_t o = (size_t)(n_off + n0 + ty + j) * out_ld + k0 + tx;
        out_hi[o] = __bfloat16_as_ushort(hb);
        out_lo[o] = __bfloat16_as_ushort(lb);
    }
}

// z selects: 0=Wa, 1=Wo, 2=WB[0:1024), 3=WB[1024:2048), 4=Wdt
__global__ __launch_bounds__(256)
void wprep_all_kernel(const float* __restrict__ Wa, const float* __restrict__ Wo,
                      const float* __restrict__ WB, const float* __restrict__ Wdt)
{
    __shared__ float t[32][33];
    const int tx = threadIdx.x & 31;
    const int ty = threadIdx.x >> 5;
    const int k0 = blockIdx.y * 32;
    const int z = blockIdx.z;
    const float* W;
    int Nw, n0 = blockIdx.x * 32, n_off;
    if (z == 0)      { W = Wa;  Nw = 1024; n_off = 0; }
    else if (z == 1) { W = Wo;  Nw = 1024; n_off = 1024; }
    else if (z == 2) { W = WB;  Nw = 2048; n_off = 2048; }
    else if (z == 3) { W = WB;  Nw = 2048; n_off = 2048; n0 += 1024; }
    else             { W = Wdt; Nw = 1024; n_off = 4096; }
    wprep_body(W, Nw, n0, n_off, k0, g_Wt_hi, g_Wt_lo, DDIM, tx, ty, t);
}

__global__ __launch_bounds__(256)
void wprep_wc_kernel(const float* __restrict__ WC)
{
    __shared__ float t[32][33];
    const int tx = threadIdx.x & 31;
    const int ty = threadIdx.x >> 5;
    wprep_body(WC, DDIM, blockIdx.x * 32, 0, blockIdx.y * 32,
               g_WCt_hi, g_WCt_lo, 2 * DDIM, tx, ty, t);
}

#define XSPLIT_BLOCKS (MDIM * DDIM / 4 / 256)   // 16384
__global__ __launch_bounds__(256)
void xsplit_bias_kernel(const float* __restrict__ x,
                        const float* __restrict__ ba, const float* __restrict__ bo,
                        const float* __restrict__ bB, const float* __restrict__ bdt)
{
    if (blockIdx.x >= XSPLIT_BLOCKS) {
        int n = (blockIdx.x - XSPLIT_BLOCKS) * 256 + threadIdx.x;
        if (n >= PRE_LD) return;
        float v;
        if (n < 1024)      v = ba[n];
        else if (n < 2048) v = bo[n - 1024];
        else if (n < 4096) v = bB[n - 2048];
        else               v = bdt[n - 4096];
        g_bias_cat[n] = v;
        return;
    }
    int i = blockIdx.x * 256 + threadIdx.x;
    float4 v = ((const float4*)x)[i];
    __nv_bfloat16 h0 = __float2bfloat16(v.x), h1 = __float2bfloat16(v.y);
    __nv_bfloat16 h2 = __float2bfloat16(v.z), h3 = __float2bfloat16(v.w);
    __nv_bfloat16 l0 = __float2bfloat16(v.x - __bfloat162float(h0));
    __nv_bfloat16 l1 = __float2bfloat16(v.y - __bfloat162float(h1));
    __nv_bfloat16 l2 = __float2bfloat16(v.z - __bfloat162float(h2));
    __nv_bfloat16 l3 = __float2bfloat16(v.w - __bfloat162float(h3));
    uint2 hv, lv;
    hv.x = (uint32_t)__bfloat16_as_ushort(h0) | ((uint32_t)__bfloat16_as_ushort(h1) << 16);
    hv.y = (uint32_t)__bfloat16_as_ushort(h2) | ((uint32_t)__bfloat16_as_ushort(h3) << 16);
    lv.x = (uint32_t)__bfloat16_as_ushort(l0) | ((uint32_t)__bfloat16_as_ushort(l1) << 16);
    lv.y = (uint32_t)__bfloat16_as_ushort(l2) | ((uint32_t)__bfloat16_as_ushort(l3) << 16);
    ((uint2*)g_xh)[i] = hv;
    ((uint2*)g_xl)[i] = lv;
}

// ---------------------------------------------------------------------------
// HMMA GEMM: C[m, n] = sum_k A[m,k]*Bt[n,k] + bias[n]   (bf16x3, fp32 acc)
// CTA 128x128, BK=32, 8 warps (warp tile 32x64), 3-stage ring, 2 CTAs/SM.
// MMA order per B-group: product-outer -> consecutive HMMAs hit different accs.
// ---------------------------------------------------------------------------
__global__ __launch_bounds__(256, 2)
void mma_gemm_kernel(const u16* __restrict__ Ah, const u16* __restrict__ Al,
                     const u16* __restrict__ Bh, const u16* __restrict__ Bl,
                     const float* __restrict__ bias, const float* __restrict__ xf32,
                     float* __restrict__ C, int K, int ldc, int do_xmul)
{
    extern __shared__ char smem[];
    const uint32_t sb = smem_u32(smem);
    const int tid = threadIdx.x;
    const int lane = tid & 31;
    const int warp = tid >> 5;
    const int wm = warp >> 1;         // 0..3
    const int wn = warp & 1;          // 0..1
    const int m0 = blockIdx.y * BM;
    const int n0 = blockIdx.x * BN;

    const u16* Abase_h = Ah + (size_t)m0 * K;
    const u16* Abase_l = Al + (size_t)m0 * K;
    const u16* Bbase_h = Bh + (size_t)n0 * K;
    const u16* Bbase_l = Bl + (size_t)n0 * K;

    const int S = K / BK;

    float acc[2][8][4];
#pragma unroll
    for (int i = 0; i < 2; i++)
#pragma unroll
        for (int j = 0; j < 8; j++)
#pragma unroll
            for (int q = 0; q < 4; q++) acc[i][j][q] = 0.f;

    // ---- stage loader: 4 tiles of 128x32 (64B rows, SW64 swizzle) ----
    auto load_stage = [&](int s) {
        const int kt = s * BK;
        const uint32_t buf = sb + (uint32_t)(s % NSTAGE) * STAGE_BYTES;
        const u16* bases[4] = {Abase_h, Abase_l, Bbase_h, Bbase_l};
#pragma unroll
        for (int t = 0; t < 4; t++) {
            const u16* base = bases[t];
            const uint32_t tb = buf + t * TILE_BYTES;
#pragma unroll
            for (int i = 0; i < 2; i++) {
                int id = tid + i * 256;        // 0..511
                int r = id >> 2;               // 0..127
                int c = id & 3;                // 16B chunk
                uint32_t sw = swz64((uint32_t)(r * 64 + c * 16));
                CPASYNC16(tb + sw, base + (size_t)r * K + kt + c * 8);
            }
        }
        CPASYNC_COMMIT();
    };

    // prologue: fill 2 stages
    load_stage(0);
    load_stage(1);

    const int arow = wm * 32 + (lane & 15);
    const int brow = wn * 64 + (lane & 15);
    const int khb  = (lane >> 4) * 16;       // byte offset of k-half

    for (int s = 0; s < S; s++) {
        if (s + 1 < S) { CPASYNC_WAIT1(); } else { CPASYNC_WAIT0(); }
        __syncthreads();   // also protects ring buffer reuse

        if (s + 2 < S) load_stage(s + 2);

        const uint32_t buf = sb + (uint32_t)(s % NSTAGE) * STAGE_BYTES;
#pragma unroll
        for (int kk = 0; kk < 2; kk++) {
            const uint32_t kb = (uint32_t)(kk * 32 + khb);
            uint32_t ah[2][4], al[2][4];
#pragma unroll
            for (int mi = 0; mi < 2; mi++) {
                uint32_t off = swz64((uint32_t)((arow + mi * 16) * 64) + kb);
                ldsm_x4(ah[mi], buf + off);
                ldsm_x4(al[mi], buf + TILE_BYTES + off);
            }
#pragma unroll
            for (int g = 0; g < 4; g++) {
                uint32_t off = swz64((uint32_t)((brow + g * 16) * 64) + kb);
                uint32_t th[4], tl[4];
                ldsm_x4(th, buf + 2 * TILE_BYTES + off);
                ldsm_x4(tl, buf + 3 * TILE_BYTES + off);
                uint32_t b0h[2] = {th[0], th[2]}, b1h[2] = {th[1], th[3]};
                uint32_t b0l[2] = {tl[0], tl[2]}, b1l[2] = {tl[1], tl[3]};
                // product-outer order: consecutive MMAs target different accs
                // per-acc sequence remains hh -> hl -> lh (rounding identical)
                mma_bf16(acc[0][2 * g],     ah[0], b0h);
                mma_bf16(acc[0][2 * g + 1], ah[0], b1h);
                mma_bf16(acc[1][2 * g],     ah[1], b0h);
                mma_bf16(acc[1][2 * g + 1], ah[1], b1h);
                mma_bf16(acc[0][2 * g],     ah[0], b0l);
                mma_bf16(acc[0][2 * g + 1], ah[0], b1l);
                mma_bf16(acc[1][2 * g],     ah[1], b0l);
                mma_bf16(acc[1][2 * g + 1], ah[1], b1l);
                mma_bf16(acc[0][2 * g],     al[0], b0h);
                mma_bf16(acc[0][2 * g + 1], al[0], b1h);
                mma_bf16(acc[1][2 * g],     al[1], b0h);
                mma_bf16(acc[1][2 * g + 1], al[1], b1h);
            }
        }
    }
    __syncthreads();

    // ---- epilogue: direct stores with bias (+ optional x multiply) ----
    const int m0w = m0 + wm * 32;
    const int n0w = n0 + wn * 64;
#pragma unroll
    for (int mi = 0; mi < 2; mi++) {
        const int r0 = m0w + mi * 16 + (lane >> 2);
        const int r1 = r0 + 8;
#pragma unroll
        for (int nj = 0; nj < 8; nj++) {
            const int cn = n0w + nj * 8 + 2 * (lane & 3);
            float b0 = bias[cn], b1 = bias[cn + 1];
            float v0 = acc[mi][nj][0] + b0;
            float v1 = acc[mi][nj][1] + b1;
            float v2 = acc[mi][nj][2] + b0;
            float v3 = acc[mi][nj][3] + b1;
            if (do_xmul && cn >= 2048 && cn < 4096) {
                const int xc = (cn - 2048) >> 1;
                float xa = xf32[(size_t)r0 * DDIM + xc];
                float xb = xf32[(size_t)r1 * DDIM + xc];
                v0 *= xa; v1 *= xa; v2 *= xb; v3 *= xb;
            }
            float2 p0 = {v0, v1}, p1 = {v2, v3};
            *(float2*)(C + (size_t)r0 * ldc + cn) = p0;
            *(float2*)(C + (size_t)r1 * ldc + cn) = p1;
        }
    }
}

// ---------------------------------------------------------------------------
// Scan
// ---------------------------------------------------------------------------
__device__ __forceinline__ float softplusf(float v)
{
    return v > 20.f ? v : log1pf(expf(v));
}

struct StepAU { float ar, ai, u0, u1; };

__device__ __forceinline__ StepAU compute_step(const float* __restrict__ row, int d)
{
    float ap  = row[d];
    float om  = row[DDIM + d];
    float bx0 = row[2 * DDIM + 2 * d];
    float bx1 = row[2 * DDIM + 2 * d + 1];
    float dtp = row[4 * DDIM + d];

    float alpha = softplusf(ap);
    float dt    = softplusf(dtp);
    float tau = 0.5f * dt;
    float opa = fmaf(tau, alpha, 1.0f);
    float tw  = tau * om;
    float inv = 1.0f / fmaf(opa, opa, fmaf(tw, tw, 1e-6f));
    float m11 = opa * inv;
    float m12 = tw * inv;
    float oma = fmaf(-tau, alpha, 1.0f);

    StepAU r;
    r.ar = fmaf(m11, oma, -m12 * tw);
    float a12 = fmaf(m11, tw, m12 * oma);
    r.ai = -a12;
    r.u0 = dt * fmaf(m11, bx0, m12 * bx1);
    r.u1 = dt * fmaf(-m12, bx0, m11 * bx1);
    return r;
}

__global__ __launch_bounds__(256)
void scan_pass1()
{
    const int bid = blockIdx.x;
    const int d = (bid & 3) * 256 + threadIdx.x;
    const int c = (bid >> 2) & (NCH - 1);
    const int b = bid >> 8;

    float Pr = 1.f, Pi = 0.f, qr = 0.f, qi = 0.f;
    const size_t row0 = ((size_t)b * SDIM + (size_t)c * LCH);
#pragma unroll 4
    for (int i = 0; i < LCH; i++) {
        StepAU s = compute_step(g_pre + (row0 + i) * PRE_LD, d);
        float nPr = s.ar * Pr - s.ai * Pi;
        float nPi = s.ar * Pi + s.ai * Pr;
        float nqr = s.ar * qr - s.ai * qi + s.u0;
        float nqi = s.ar * qi + s.ai * qr + s.u1;
        Pr = nPr; Pi = nPi; qr = nqr; qi = nqi;
    }
    const size_t o = (((size_t)b * NCH + c) * 2) * DDIM + d;
    g_P[o] = Pr; g_P[o + DDIM] = Pi;
    g_Q[o] = qr; g_Q[o + DDIM] = qi;
}

__global__ __launch_bounds__(256)
void scan_pass2(const float* __restrict__ state, float* __restrict__ fs)
{
    const int b = blockIdx.x >> 2;
    const int d = (blockIdx.x & 3) * 256 + threadIdx.x;

    float hr = state[((size_t)b * DDIM + d) * 2 + 0];
    float hi = state[((size_t)b * DDIM + d) * 2 + 1];
#pragma unroll 4
    for (int c = 0; c < NCH; c++) {
        const size_t o = (((size_t)b * NCH + c) * 2) * DDIM + d;
        g_h0[o] = hr; g_h0[o + DDIM] = hi;
        float Pr = g_P[o], Pi = g_P[o + DDIM];
        float qr = g_Q[o], qi = g_Q[o + DDIM];
        float nr = Pr * hr - Pi * hi + qr;
        float ni = Pr * hi + Pi * hr + qi;
        hr = nr; hi = ni;
    }
    if (fs) {
        fs[((size_t)b * DDIM + d) * 2 + 0] = hr;
        fs[((size_t)b * DDIM + d) * 2 + 1] = hi;
    }
}

// pass 3: regenerate per-step states, emit as bf16 hi/lo (A operand of GEMM2)
__global__ __launch_bounds__(256)
void scan_pass3()
{
    const int bid = blockIdx.x;
    const int d = (bid & 3) * 256 + threadIdx.x;
    const int c = (bid >> 2) & (NCH - 1);
    const int b = bid >> 8;

    const size_t o = (((size_t)b * NCH + c) * 2) * DDIM + d;
    float hr = g_h0[o], hi = g_h0[o + DDIM];
    const size_t row0 = ((size_t)b * SDIM + (size_t)c * LCH);
#pragma unroll 4
    for (int i = 0; i < LCH; i++) {
        StepAU s = compute_step(g_pre + (row0 + i) * PRE_LD, d);
        float nr = s.ar * hr - s.ai * hi + s.u0;
        float ni = s.ar * hi + s.ai * hr + s.u1;
        hr = nr; hi = ni;
        __nv_bfloat16 hh = __float2bfloat16(hr);
        __nv_bfloat16 ih = __float2bfloat16(hi);
        __nv_bfloat16 hl = __float2bfloat16(hr - __bfloat162float(hh));
        __nv_bfloat16 il = __float2bfloat16(hi - __bfloat162float(ih));
        uint32_t hp = (uint32_t)__bfloat16_as_ushort(hh) | ((uint32_t)__bfloat16_as_ushort(ih) << 16);
        uint32_t lp = (uint32_t)__bfloat16_as_ushort(hl) | ((uint32_t)__bfloat16_as_ushort(il) << 16);
        ((uint32_t*)g_sth)[(row0 + i) * DDIM + d] = hp;
        ((uint32_t*)g_stl)[(row0 + i) * DDIM + d] = lp;
    }
}

// ---------------------------------------------------------------------------
// launch
// ---------------------------------------------------------------------------
extern "C" void kernel_launch(void* const* d_in, const int* in_sizes, int n_in,
                              void* d_out, int out_size)
{
    const float* x     = (const float*)d_in[0];
    const float* state = (const float*)d_in[1];
    const float* Wa    = (const float*)d_in[2];
    const float* ba    = (const float*)d_in[3];
    const float* Wo    = (const float*)d_in[4];
    const float* bo    = (const float*)d_in[5];
    const float* WB    = (const float*)d_in[6];
    const float* bB    = (const float*)d_in[7];
    const float* Wdt   = (const float*)d_in[8];
    const float *bdt, *WC, *bC;
    if (n_in >= 12 && in_sizes[9] == 1024) {
        bdt = (const float*)d_in[9];
        WC  = (const float*)d_in[10];
        bC  = (const float*)d_in[11];
    } else {
        WC  = (const float*)d_in[9];
        bC  = (const float*)d_in[10];
        bdt = (const float*)d_in[11];
    }
    float* out = (float*)d_out;

    float* pre = nullptr;
    u16 *wth, *wtl, *wcth, *wctl, *xh, *xl, *sth, *stl;
    cudaGetSymbolAddress((void**)&pre, g_pre);
    cudaGetSymbolAddress((void**)&wth, g_Wt_hi);
    cudaGetSymbolAddress((void**)&wtl, g_Wt_lo);
    cudaGetSymbolAddress((void**)&wcth, g_WCt_hi);
    cudaGetSymbolAddress((void**)&wctl, g_WCt_lo);
    cudaGetSymbolAddress((void**)&xh, g_xh);
    cudaGetSymbolAddress((void**)&xl, g_xl);
    cudaGetSymbolAddress((void**)&sth, g_sth);
    cudaGetSymbolAddress((void**)&stl, g_stl);
    float* bias_cat = nullptr;
    cudaGetSymbolAddress((void**)&bias_cat, g_bias_cat);

    float* fs = (out_size >= MDIM * DDIM + BDIM * DDIM * 2)
                ? out + (size_t)MDIM * DDIM : nullptr;

    cudaFuncSetAttribute(mma_gemm_kernel, cudaFuncAttributeMaxDynamicSharedMemorySize, SM_TOTAL);

    const dim3 t(256);
    // launches 1-3 (prep); gemm1 is launch #4 — the slot ncu profiled last round
    wprep_all_kernel<<<dim3(32, 32, 5), t>>>(Wa, Wo, WB, Wdt);          // 1
    wprep_wc_kernel<<<dim3(32, 64), t>>>(WC);                           // 2
    xsplit_bias_kernel<<<XSPLIT_BLOCKS + 20, t>>>(x, ba, bo, bB, bdt);  // 3

    // pre-activation GEMM (M=16384, N=5120, K=1024)                    // 4
    mma_gemm_kernel<<<dim3(PRE_LD / BN, MDIM / BM), t, SM_TOTAL>>>(
        xh, xl, wth, wtl, bias_cat, x, pre, DDIM, PRE_LD, 1);

    // chunked scan                                                     // 5,6,7
    scan_pass1<<<BDIM * NCH * (DDIM / 256), t>>>();
    scan_pass2<<<BDIM * (DDIM / 256), t>>>(state, fs);
    scan_pass3<<<BDIM * NCH * (DDIM / 256), t>>>();

    // output GEMM (M=16384, N=1024, K=2048)                            // 8
    mma_gemm_kernel<<<dim3(DDIM / BN, MDIM / BM), t, SM_TOTAL>>>(
        sth, stl, wcth, wctl, bC, nullptr, out, 2 * DDIM, DDIM, 0);
}